// round 15
// baseline (speedup 1.0000x reference)
#include <cuda_runtime.h>
#include <cuda_bf16.h>
#include <cstddef>

#define BATCH 256
#define SEQ   512
#define DIN   64
#define HID   512
#define GRIDN 128
#define NTH   512

#define TM 64
#define TN 64
#define KA_PER 144          // 576 / 4
#define KB_PER 256          // 1024 / 4
#define NC_A 9
#define NC_B 16

#define SA 152              // A-phase row stride (bf16 elems)
#define SB 264              // B-phase row stride

#define OFF_WA_HI 0
#define OFF_WA_LO (OFF_WA_HI + 64 * SA)
#define OFF_AA_HI (OFF_WA_LO + 64 * SA)
#define OFF_AA_LO (OFF_AA_HI + 64 * SA)
#define OFF_WB_HI (OFF_AA_LO + 64 * SA)
#define OFF_WB_LO (OFF_WB_HI + 64 * SB)
#define OFF_AB_HI (OFF_WB_LO + 64 * SB)
#define OFF_AB_LO (OFF_AB_HI + 64 * SB)
#define ELEMS_TOT (OFF_AB_LO + 64 * SB)          // 106,496 bf16 = 212,992 B
#define SCR_STRIDE 68                            // fp32; rows 16B-aligned
#define SMEM_BYTES (ELEMS_TOT * 2 + 64 * SCR_STRIDE * 4)   // 230,400 B

typedef unsigned long long ull;

// ---------------- cross-CTA state (static scratch; allocation-free) ----------------
__device__ __nv_bfloat16 g_Xhi[BATCH * SEQ * DIN];
__device__ __nv_bfloat16 g_Xlo[BATCH * SEQ * DIN];
__device__ __nv_bfloat16 g_H1hi[2][BATCH * HID], g_H1lo[2][BATCH * HID];
__device__ __nv_bfloat16 g_H2hi[2][BATCH * HID], g_H2lo[2][BATCH * HID];

struct __align__(128) Line { unsigned v; unsigned pad[31]; };
__device__ Line g_leaf[8];
__device__ Line g_root;
__device__ Line g_gen;
__device__ Line g_flag[GRIDN];   // per-CTA step flags (zero-init)

// full-grid tree barrier (init only)
__device__ __forceinline__ void grid_sync_init(int leaf) {
    __syncthreads();
    if (threadIdx.x == 0) {
        unsigned gen = *(volatile unsigned*)&g_gen.v;
        __threadfence();
        if (atomicAdd(&g_leaf[leaf].v, 1u) == 15u) {
            g_leaf[leaf].v = 0u;
            __threadfence();
            if (atomicAdd(&g_root.v, 1u) == 7u) {
                g_root.v = 0u;
                __threadfence();
                *(volatile unsigned*)&g_gen.v = gen + 1u;
            } else {
                while (*(volatile unsigned*)&g_gen.v == gen) __nanosleep(16);
            }
        } else {
            while (*(volatile unsigned*)&g_gen.v == gen) __nanosleep(16);
        }
        __threadfence();
    }
    __syncthreads();
}

#define CLUSTER_SYNC() do { \
    asm volatile("barrier.cluster.arrive.aligned;" ::: "memory"); \
    asm volatile("barrier.cluster.wait.aligned;" ::: "memory"); \
} while (0)

__device__ __forceinline__ unsigned mapa_rank(unsigned smaddr, unsigned rank) {
    unsigned r;
    asm("mapa.shared::cluster.u32 %0, %1, %2;" : "=r"(r) : "r"(smaddr), "r"(rank));
    return r;
}
__device__ __forceinline__ float2 ld_dsmem_f2(unsigned addr) {
    float2 v;
    asm volatile("ld.shared::cluster.v2.f32 {%0,%1}, [%2];"
                 : "=f"(v.x), "=f"(v.y) : "r"(addr));
    return v;
}

__device__ __forceinline__ void mma16816(float* c, const unsigned* a, const unsigned* b) {
    asm volatile(
        "mma.sync.aligned.m16n8k16.row.col.f32.bf16.bf16.f32 "
        "{%0,%1,%2,%3}, {%4,%5,%6,%7}, {%8,%9}, {%0,%1,%2,%3};"
        : "+f"(c[0]), "+f"(c[1]), "+f"(c[2]), "+f"(c[3])
        : "r"(a[0]), "r"(a[1]), "r"(a[2]), "r"(a[3]), "r"(b[0]), "r"(b[1]));
}

__device__ __forceinline__ void ldsm_x4(unsigned& r0, unsigned& r1,
                                        unsigned& r2, unsigned& r3, unsigned addr) {
    asm volatile("ldmatrix.sync.aligned.m8n8.x4.shared.b16 {%0,%1,%2,%3}, [%4];"
                 : "=r"(r0), "=r"(r1), "=r"(r2), "=r"(r3) : "r"(addr));
}

#define CP16(dst_u32, src_ptr) \
    asm volatile("cp.async.cg.shared.global [%0], [%1], 16;" \
                 :: "r"(dst_u32), "l"(src_ptr))
#define CP_COMMIT() asm volatile("cp.async.commit_group;")
#define CP_WAIT(n)  asm volatile("cp.async.wait_group %0;" :: "n"(n))

__device__ __forceinline__ void split_bf16(float v, __nv_bfloat16& hi, __nv_bfloat16& lo) {
    hi = __float2bfloat16_rn(v);
    lo = __float2bfloat16_rn(v - __bfloat162float(hi));
}

__global__ void __launch_bounds__(NTH, 1) __cluster_dims__(4, 1, 1) rnn_hmma(
    const float* __restrict__ x,
    const float* __restrict__ W_ih0, const float* __restrict__ W_hh0,
    const float* __restrict__ b_ih0, const float* __restrict__ b_hh0,
    const float* __restrict__ W_ih1, const float* __restrict__ W_hh1,
    const float* __restrict__ b_ih1, const float* __restrict__ b_hh1,
    const float* __restrict__ W_fc,  const float* __restrict__ b_fc,
    float* __restrict__ out)
{
    const int tid  = threadIdx.x;
    const int bid  = blockIdx.x;
    const int leaf = bid & 7;
    const int grp  = bid >> 5;
    const int ks   = bid & 3;
    const int tile = bid >> 2;
    const int mt   = tile >> 3;
    const int nt   = tile & 7;
    const int m0   = mt * TM;
    const int n0   = nt * TN;

    extern __shared__ __nv_bfloat16 sm[];
    float* scrA = (float*)(sm + ELEMS_TOT);
    float* scrB = (float*)(sm + OFF_AA_HI);      // aliases AA staging (dead in phase B)
    const unsigned sm_u32   = (unsigned)__cvta_generic_to_shared(sm);
    const unsigned scrA_u32 = sm_u32 + ELEMS_TOT * 2;
    const unsigned scrB_u32 = sm_u32 + OFF_AA_HI * 2;

    unsigned stepno = 1;

    // ---------- one-time: split weight slices -> SMEM ----------
    {
        const int kb = ks * KA_PER;
        for (int idx = tid; idx < 64 * KA_PER; idx += NTH) {
            int n = idx / KA_PER, k = idx - n * KA_PER;
            int kg = kb + k;
            float v = (kg < DIN) ? W_ih0[(n0 + n) * DIN + kg]
                                 : W_hh0[(n0 + n) * HID + (kg - DIN)];
            __nv_bfloat16 hi, lo; split_bf16(v, hi, lo);
            sm[OFF_WA_HI + n * SA + k] = hi;
            sm[OFF_WA_LO + n * SA + k] = lo;
        }
        const int kbb = ks * KB_PER;
        for (int idx = tid; idx < 64 * KB_PER; idx += NTH) {
            int n = idx / KB_PER, k = idx - n * KB_PER;
            int kg = kbb + k;
            float v = (kg < HID) ? W_ih1[(n0 + n) * HID + kg]
                                 : W_hh1[(n0 + n) * HID + (kg - HID)];
            __nv_bfloat16 hi, lo; split_bf16(v, hi, lo);
            sm[OFF_WB_HI + n * SB + k] = hi;
            sm[OFF_WB_LO + n * SB + k] = lo;
        }
    }
    // ---------- one-time: pre-split x ----------
    {
        const int total = BATCH * SEQ * DIN;
        for (int i = (bid * NTH + tid) * 4; i < total; i += GRIDN * NTH * 4) {
            float4 v = *(const float4*)(x + i);
            __nv_bfloat16 h0,h1,h2,h3,l0,l1,l2,l3;
            split_bf16(v.x,h0,l0); split_bf16(v.y,h1,l1);
            split_bf16(v.z,h2,l2); split_bf16(v.w,h3,l3);
            *(__nv_bfloat162*)(g_Xhi + i)     = __halves2bfloat162(h0, h1);
            *(__nv_bfloat162*)(g_Xhi + i + 2) = __halves2bfloat162(h2, h3);
            *(__nv_bfloat162*)(g_Xlo + i)     = __halves2bfloat162(l0, l1);
            *(__nv_bfloat162*)(g_Xlo + i + 2) = __halves2bfloat162(l2, l3);
        }
    }
    // ---------- zero t=-1 states (buffer 1) ----------
    {
        const int per = (BATCH * HID) / GRIDN;   // 1024
        const int base = bid * per;
        __nv_bfloat162 z = __halves2bfloat162(__float2bfloat16(0.f), __float2bfloat16(0.f));
        for (int i = tid * 2; i < per; i += NTH * 2) {
            *(__nv_bfloat162*)(&g_H1hi[1][base + i]) = z;
            *(__nv_bfloat162*)(&g_H1lo[1][base + i]) = z;
            *(__nv_bfloat162*)(&g_H2hi[1][base + i]) = z;
            *(__nv_bfloat162*)(&g_H2lo[1][base + i]) = z;
        }
    }
    grid_sync_init(leaf);

    // ---------- flag barrier ----------
    auto group_flag_bar = [&]() {
        __syncthreads();
        if (tid == 0) {
            __threadfence();
            *(volatile unsigned*)&g_flag[bid].v = stepno;
        }
        if (tid < 32) {
            volatile unsigned* f = &g_flag[(grp << 5) + tid].v;
            while (*f < stepno) { __nanosleep(8); }
        }
        __syncthreads();
        __threadfence();
        stepno++;
    };

    // ---------- roles ----------
    const int lane = tid & 31;
    const int wid  = tid >> 5;        // 0..15
    const int wm   = wid >> 2;        // m-quarter (0..3), 16 rows
    const int wn4  = wid & 3;         // n-quarter (0..3), 16 cols
    const int q    = lane >> 2;
    const int tg2  = (lane & 3) * 2;

    const int s_k   = lane * 8;
    const int s_row = wid;            // staging row base (0..15), step 16

    // ldmatrix lane offsets
    const int a_row = lane & 15;
    const int a_col = (lane & 16) >> 1;
    const int b_row = ((lane & 16) >> 1) + (lane & 7);
    const int b_col = lane & 8;

    // reduce role: 2048 cluster threads, one float2 each (64 x 32 units)
    const int gtid = ks * NTH + tid;          // 0..2047
    const int rr  = gtid >> 5;                // 0..63
    const int cc2 = (gtid & 31) << 1;         // 0..62
    float2 biasA, biasB;
    {
        float2 bi = *(const float2*)(b_ih0 + n0 + cc2);
        float2 bh = *(const float2*)(b_hh0 + n0 + cc2);
        biasA = make_float2(bi.x + bh.x, bi.y + bh.y);
        bi = *(const float2*)(b_ih1 + n0 + cc2);
        bh = *(const float2*)(b_hh1 + n0 + cc2);
        biasB = make_float2(bi.x + bh.x, bi.y + bh.y);
    }
    const unsigned redoff = (unsigned)(rr * SCR_STRIDE + cc2) * 4u;

    // ---------- async staging (16 warps, 4 rows each) ----------
    auto stageA_async = [&](int t, const __nv_bfloat16* h1phi, const __nv_bfloat16* h1plo) {
        if (s_k < KA_PER) {
            const int kg = ks * KA_PER + s_k;
            #pragma unroll
            for (int it = 0; it < 4; ++it) {
                int row = s_row + it * 16;
                int mgr = m0 + row;
                const __nv_bfloat16 *ph, *pl;
                if (kg < DIN) {
                    size_t off = (size_t)mgr * (SEQ * DIN) + (size_t)t * DIN + kg;
                    ph = g_Xhi + off; pl = g_Xlo + off;
                } else {
                    size_t off = (size_t)mgr * HID + (kg - DIN);
                    ph = h1phi + off; pl = h1plo + off;
                }
                CP16(sm_u32 + (OFF_AA_HI + row * SA + s_k) * 2, ph);
                CP16(sm_u32 + (OFF_AA_LO + row * SA + s_k) * 2, pl);
            }
        }
        CP_COMMIT();
    };
    auto stageB_async = [&](const __nv_bfloat16* h1phi, const __nv_bfloat16* h1plo,
                            const __nv_bfloat16* h2phi, const __nv_bfloat16* h2plo) {
        const int kg = ks * KB_PER + s_k;
        const int koff = (ks < 2) ? kg : kg - HID;
        const __nv_bfloat16* shi = (ks < 2) ? h1phi : h2phi;
        const __nv_bfloat16* slo = (ks < 2) ? h1plo : h2plo;
        #pragma unroll
        for (int it = 0; it < 4; ++it) {
            int row = s_row + it * 16;
            size_t off = (size_t)(m0 + row) * HID + koff;
            CP16(sm_u32 + (OFF_AB_HI + row * SB + s_k) * 2, shi + off);
            CP16(sm_u32 + (OFF_AB_LO + row * SB + s_k) * 2, slo + off);
        }
        CP_COMMIT();
    };

    // ---------- GEMM phase: full-K per warp (4m x 4n, 16x16 tile), direct scr store ----------
    auto computePhase = [&](int offWhi, int offWlo, int offAhi, int offAlo, int st,
                            int NC, float* __restrict__ scrp) {
        float acc[2][4];
        #pragma unroll
        for (int g = 0; g < 2; g++)
            #pragma unroll
            for (int i = 0; i < 4; i++) acc[g][i] = 0.f;

        unsigned aHiB, aLoB, bHiB, bLoB;
        {
            unsigned roff = (unsigned)((wm * 16 + a_row) * st + a_col);
            aHiB = sm_u32 + (offAhi + roff) * 2;
            aLoB = sm_u32 + (offAlo + roff) * 2;
            roff = (unsigned)((wn4 * 16 + b_row) * st + b_col);
            bHiB = sm_u32 + (offWhi + roff) * 2;
            bLoB = sm_u32 + (offWlo + roff) * 2;
        }

        #pragma unroll 4
        for (int kst = 0; kst < NC; ++kst) {
            const unsigned kadv = (unsigned)kst * 32u;   // 16 elems * 2 bytes
            unsigned ah[4], al[4], bh[2][2], bl[2][2];
            ldsm_x4(ah[0], ah[1], ah[2], ah[3], aHiB + kadv);
            ldsm_x4(al[0], al[1], al[2], al[3], aLoB + kadv);
            ldsm_x4(bh[0][0], bh[0][1], bh[1][0], bh[1][1], bHiB + kadv);
            ldsm_x4(bl[0][0], bl[0][1], bl[1][0], bl[1][1], bLoB + kadv);
            #pragma unroll
            for (int g = 0; g < 2; g++) {
                mma16816(acc[g], ah, bh[g]);
                mma16816(acc[g], al, bh[g]);
                mma16816(acc[g], ah, bl[g]);
            }
        }
        // direct store: warp owns rows wm*16..+15, cols wn4*16..+15
        #pragma unroll
        for (int g = 0; g < 2; g++) {
            int r = wm * 16 + q;
            int c = wn4 * 16 + g * 8 + tg2;
            *(float2*)(scrp + r * SCR_STRIDE + c) =
                make_float2(acc[g][0], acc[g][1]);
            *(float2*)(scrp + (r + 8) * SCR_STRIDE + c) =
                make_float2(acc[g][2], acc[g][3]);
        }
    };

    // tanh + split + store (2 values)
    auto finishH2 = [&](float2 s, __nv_bfloat16* __restrict__ dhi,
                        __nv_bfloat16* __restrict__ dlo) {
        float h0 = tanhf(s.x), h1 = tanhf(s.y);
        __nv_bfloat16 hi0, hi1, lo0, lo1;
        split_bf16(h0, hi0, lo0); split_bf16(h1, hi1, lo1);
        __nv_bfloat162 ph = __halves2bfloat162(hi0, hi1);
        __nv_bfloat162 pl = __halves2bfloat162(lo0, lo1);
        size_t doff = (size_t)(m0 + rr) * HID + n0 + cc2;
        __stcg((unsigned*)(dhi + doff), *(unsigned*)&ph);
        __stcg((unsigned*)(dlo + doff), *(unsigned*)&pl);
    };

    // merged reduce: all 8 DSMEM loads first, then tanh + stores
    auto reduceAB = [&](bool doB,
                        __nv_bfloat16* d1hi, __nv_bfloat16* d1lo,
                        __nv_bfloat16* d2hi, __nv_bfloat16* d2lo) {
        const unsigned aA = scrA_u32 + redoff;
        const unsigned aB = scrB_u32 + redoff;
        float2 a0 = ld_dsmem_f2(mapa_rank(aA, 0));
        float2 a1 = ld_dsmem_f2(mapa_rank(aA, 1));
        float2 a2 = ld_dsmem_f2(mapa_rank(aA, 2));
        float2 a3 = ld_dsmem_f2(mapa_rank(aA, 3));
        float2 b0, b1, b2, b3;
        if (doB) {
            b0 = ld_dsmem_f2(mapa_rank(aB, 0));
            b1 = ld_dsmem_f2(mapa_rank(aB, 1));
            b2 = ld_dsmem_f2(mapa_rank(aB, 2));
            b3 = ld_dsmem_f2(mapa_rank(aB, 3));
        }
        float2 s;
        s.x = biasA.x + a0.x + a1.x + a2.x + a3.x;
        s.y = biasA.y + a0.y + a1.y + a2.y + a3.y;
        finishH2(s, d1hi, d1lo);
        if (doB) {
            s.x = biasB.x + b0.x + b1.x + b2.x + b3.x;
            s.y = biasB.y + b0.y + b1.y + b2.y + b3.y;
            finishH2(s, d2hi, d2lo);
        }
    };

    // ============================ main loop ============================
    for (int t = 0; t < SEQ; ++t) {
        const int pp = (t + 1) & 1, pc = t & 1;
        const __nv_bfloat16* h1phi = g_H1hi[pp]; const __nv_bfloat16* h1plo = g_H1lo[pp];
        const __nv_bfloat16* h2phi = g_H2hi[pc]; const __nv_bfloat16* h2plo = g_H2lo[pc];

        stageA_async(t, h1phi, h1plo);
        if (t > 0) {
            stageB_async(h1phi, h1plo, h2phi, h2plo);
            CP_WAIT(1);
        } else {
            CP_WAIT(0);
        }
        __syncthreads();
        computePhase(OFF_WA_HI, OFF_WA_LO, OFF_AA_HI, OFF_AA_LO, SA, NC_A, scrA);
        if (t > 0) {
            CP_WAIT(0);
            __syncthreads();               // AB staged visible; all warps past computeA
            computePhase(OFF_WB_HI, OFF_WB_LO, OFF_AB_HI, OFF_AB_LO, SB, NC_B, scrB);
        }
        CLUSTER_SYNC();                    // scrA + scrB visible cluster-wide
        reduceAB(t > 0, g_H1hi[pc], g_H1lo[pc], g_H2hi[pp], g_H2lo[pp]);
        group_flag_bar();
    }
    // epilogue: B(511): h1(511) in buf1, h2(510) in buf0 -> h2(511) in buf1
    stageB_async(g_H1hi[1], g_H1lo[1], g_H2hi[0], g_H2lo[0]);
    CP_WAIT(0);
    __syncthreads();
    computePhase(OFF_WB_HI, OFF_WB_LO, OFF_AB_HI, OFF_AB_LO, SB, NC_B, scrB);
    CLUSTER_SYNC();
    {
        const unsigned aB = scrB_u32 + redoff;
        float2 b0 = ld_dsmem_f2(mapa_rank(aB, 0));
        float2 b1 = ld_dsmem_f2(mapa_rank(aB, 1));
        float2 b2 = ld_dsmem_f2(mapa_rank(aB, 2));
        float2 b3 = ld_dsmem_f2(mapa_rank(aB, 3));
        float2 s;
        s.x = biasB.x + b0.x + b1.x + b2.x + b3.x;
        s.y = biasB.y + b0.y + b1.y + b2.y + b3.y;
        finishH2(s, g_H2hi[1], g_H2lo[1]);
    }
    group_flag_bar();

    // ============================ final FC ============================
    static __shared__ float red[16];
    for (int r = 0; r < 2; ++r) {
        int b = bid * 2 + r;
        float s = 0.f;
        for (int h = tid * 2; h < HID; h += NTH * 2) {
            unsigned uh = __ldcg((const unsigned*)(&g_H2hi[1][(size_t)b * HID + h]));
            unsigned ul = __ldcg((const unsigned*)(&g_H2lo[1][(size_t)b * HID + h]));
            __nv_bfloat162 vh = *(__nv_bfloat162*)&uh;
            __nv_bfloat162 vl = *(__nv_bfloat162*)&ul;
            float v0 = __bfloat162float(__low2bfloat16(vh)) + __bfloat162float(__low2bfloat16(vl));
            float v1 = __bfloat162float(__high2bfloat16(vh)) + __bfloat162float(__high2bfloat16(vl));
            s += v0 * W_fc[h] + v1 * W_fc[h + 1];
        }
        #pragma unroll
        for (int off = 16; off; off >>= 1)
            s += __shfl_down_sync(0xffffffffu, s, off);
        if ((tid & 31) == 0) red[tid >> 5] = s;
        __syncthreads();
        if (tid == 0) {
            float tot = b_fc[0];
            #pragma unroll
            for (int w = 0; w < 16; w++) tot += red[w];
            out[b] = tot;
        }
        __syncthreads();
    }
}

extern "C" void kernel_launch(void* const* d_in, const int* in_sizes, int n_in,
                              void* d_out, int out_size) {
    (void)in_sizes; (void)n_in; (void)out_size;
    const float* x     = (const float*)d_in[0];
    const float* W_ih0 = (const float*)d_in[1];
    const float* W_hh0 = (const float*)d_in[2];
    const float* b_ih0 = (const float*)d_in[3];
    const float* b_hh0 = (const float*)d_in[4];
    const float* W_ih1 = (const float*)d_in[5];
    const float* W_hh1 = (const float*)d_in[6];
    const float* b_ih1 = (const float*)d_in[7];
    const float* b_hh1 = (const float*)d_in[8];
    const float* W_fc  = (const float*)d_in[9];
    const float* b_fc  = (const float*)d_in[10];
    float* out = (float*)d_out;

    cudaFuncSetAttribute(rnn_hmma,
                         cudaFuncAttributeMaxDynamicSharedMemorySize, SMEM_BYTES);
    rnn_hmma<<<GRIDN, NTH, SMEM_BYTES>>>(
        x, W_ih0, W_hh0, b_ih0, b_hh0,
        W_ih1, W_hh1, b_ih1, b_hh1, W_fc, b_fc, out);
}